// round 14
// baseline (speedup 1.0000x reference)
#include <cuda_runtime.h>
#include <math.h>

#define NN 50000
#define NEDGE 800000
#define F 128
#define SCAN_T 1024
#define CHUNK ((NN + SCAN_T - 1) / SCAN_T)

// ---- scratch (static device globals; no allocation anywhere) ----
__device__ float g_h[(size_t)NN * F];     // transformed features
__device__ float g_x2[(size_t)NN * F];    // layer-2 input
__device__ float g_as[NN * 8];            // alpha_src per node/head
__device__ float g_ad[NN * 8];            // alpha_dst per node/head
__device__ float g_gmax[2][8];            // per-layer global per-head max of g_as
__device__ int   g_cnt[NN];               // in-degree counts
__device__ int   g_off[NN + 1];           // CSR offsets (by dst)
__device__ int   g_cur[NN];               // scatter cursors
__device__ int   g_csrc[NEDGE];           // CSR src indices

__device__ __forceinline__ float lrelu(float v) { return v >= 0.f ? v : 0.2f * v; }

__device__ __forceinline__ void atomicMaxF(float* a, float v) {
    if (v >= 0.f) atomicMax((int*)a, __float_as_int(v));
    else          atomicMin((unsigned int*)a, __float_as_uint(v));
}
__device__ __forceinline__ void atomicMaxFs(float* a, float v) {  // shared-mem
    if (v >= 0.f) atomicMax((int*)a, __float_as_int(v));
    else          atomicMin((unsigned int*)a, __float_as_uint(v));
}

// ================= CSR build (once per launch, shared by both layers) ========
// vectorized zero + both layers' gmax init
__global__ void zero_cnt() {
    int i = blockIdx.x * blockDim.x + threadIdx.x;
    if (i < NN / 4) ((int4*)g_cnt)[i] = make_int4(0, 0, 0, 0);
    if (i < 16) g_gmax[i >> 3][i & 7] = -INFINITY;
}

// 4 edges per thread: 4 independent atomic chains -> 4x MLP
__global__ void count_edges(const int* __restrict__ ei) {
    int e = (blockIdx.x * blockDim.x + threadIdx.x) * 4;
    if (e >= NEDGE) return;
    int4 d4 = *(const int4*)(ei + NEDGE + e);
    atomicAdd(&g_cnt[d4.x], 1);
    atomicAdd(&g_cnt[d4.y], 1);
    atomicAdd(&g_cnt[d4.z], 1);
    atomicAdd(&g_cnt[d4.w], 1);
}

__global__ void scan_offsets() {
    __shared__ int partial[SCAN_T];
    int t = threadIdx.x;
    int start = t * CHUNK;
    int end = min(start + CHUNK, NN);
    int s = 0;
    for (int i = start; i < end; i++) s += g_cnt[i];
    partial[t] = s;
    __syncthreads();
    for (int off = 1; off < SCAN_T; off <<= 1) {
        int v = (t >= off) ? partial[t - off] : 0;
        __syncthreads();
        partial[t] += v;
        __syncthreads();
    }
    int run = partial[t] - s;   // exclusive prefix at chunk start
    for (int i = start; i < end; i++) {
        g_off[i] = run;
        g_cur[i] = run;
        run += g_cnt[i];
    }
    if (t == SCAN_T - 1) g_off[NN] = partial[SCAN_T - 1];
}

// 4 edges per thread
__global__ void scatter_edges(const int* __restrict__ ei) {
    int e = (blockIdx.x * blockDim.x + threadIdx.x) * 4;
    if (e >= NEDGE) return;
    int4 s4 = *(const int4*)(ei + e);
    int4 d4 = *(const int4*)(ei + NEDGE + e);
    int p0 = atomicAdd(&g_cur[d4.x], 1);
    int p1 = atomicAdd(&g_cur[d4.y], 1);
    int p2 = atomicAdd(&g_cur[d4.z], 1);
    int p3 = atomicAdd(&g_cur[d4.w], 1);
    g_csrc[p0] = s4.x;
    g_csrc[p1] = s4.y;
    g_csrc[p2] = s4.z;
    g_csrc[p3] = s4.w;
}

// ================= GEMM h = x @ W, fused alpha + gmax epilogue ===============
// block = 256 threads (8 warps), 64 rows/block, 8 rows/warp, 4 cols/lane.
// Scalar FFMA; higher FMA:LDS issue ratio (32:12 per warp per k) vs R13 (16:8).
__global__ void gemm_alpha(const float* __restrict__ xin, int layer,
                           const float* __restrict__ W,
                           const float* __restrict__ asr,
                           const float* __restrict__ adr)
{
    const float* x = layer ? g_x2 : xin;
    __shared__ float Wsh[64 * 128];   // 32 KB: 64 k-rows x 128 cols
    __shared__ float Xsh[64 * 64];    // 16 KB: 64 rows x 64 k
    __shared__ float red[8];
    int tid  = threadIdx.x;
    int warp = tid >> 5, lane = tid & 31;
    int row0 = blockIdx.x * 64;
    if (tid < 8) red[tid] = -INFINITY;
    float acc[8][4];
#pragma unroll
    for (int r = 0; r < 8; r++)
#pragma unroll
        for (int c = 0; c < 4; c++) acc[r][c] = 0.f;

    for (int kb = 0; kb < 128; kb += 64) {
        for (int i = tid; i < 2048; i += 256)
            ((float4*)Wsh)[i] = ((const float4*)(W + kb * 128))[i];
        for (int i = tid; i < 1024; i += 256) {
            int r = i >> 4, c4 = i & 15;
            int row = row0 + r;
            float4 v = make_float4(0.f, 0.f, 0.f, 0.f);
            if (row < NN) v = *(const float4*)(x + (size_t)row * 128 + kb + c4 * 4);
            ((float4*)Xsh)[i] = v;
        }
        __syncthreads();
#pragma unroll 4
        for (int k = 0; k < 64; k++) {
            float4 wv = ((float4*)Wsh)[k * 32 + lane];
#pragma unroll
            for (int r = 0; r < 8; r++) {
                float xv = Xsh[(warp * 8 + r) * 64 + k];
                acc[r][0] = fmaf(xv, wv.x, acc[r][0]);
                acc[r][1] = fmaf(xv, wv.y, acc[r][1]);
                acc[r][2] = fmaf(xv, wv.z, acc[r][2]);
                acc[r][3] = fmaf(xv, wv.w, acc[r][3]);
            }
        }
        __syncthreads();
    }

    float4 a_s = ((const float4*)asr)[lane];
    float4 a_d = ((const float4*)adr)[lane];
#pragma unroll
    for (int r = 0; r < 8; r++) {
        int row = row0 + warp * 8 + r;
        if (row >= NN) continue;
        float4 v = make_float4(acc[r][0], acc[r][1], acc[r][2], acc[r][3]);
        ((float4*)(g_h + (size_t)row * 128))[lane] = v;
        float ps = v.x * a_s.x + v.y * a_s.y + v.z * a_s.z + v.w * a_s.w;
        float pd = v.x * a_d.x + v.y * a_d.y + v.z * a_d.z + v.w * a_d.w;
        ps += __shfl_down_sync(0xffffffffu, ps, 2);
        ps += __shfl_down_sync(0xffffffffu, ps, 1);
        pd += __shfl_down_sync(0xffffffffu, pd, 2);
        pd += __shfl_down_sync(0xffffffffu, pd, 1);
        if ((lane & 3) == 0) {
            int head = lane >> 2;
            g_as[row * 8 + head] = ps;
            g_ad[row * 8 + head] = pd;
            atomicMaxFs(&red[head], ps);
        }
    }
    __syncthreads();
    if (tid < 8) atomicMaxF(&g_gmax[layer][tid], red[tid]);
}

// ================= gather aggregation (warp per dst node) ====================
// lane owns 4 channels (head = lane>>2); register accumulation; no atomics.
// Fused: softmax (shifted), normalize, +bias, ELU, output write.
__global__ void gat_gather(const float* __restrict__ bias,
                           float* __restrict__ out, int layer)
{
    int d    = (int)((blockIdx.x * (size_t)blockDim.x + threadIdx.x) >> 5);
    int lane = threadIdx.x & 31;
    if (d >= NN) return;
    int head = lane >> 2;

    float adv = g_ad[d * 8 + head];
    float mp  = lrelu(g_gmax[layer][head] + adv);   // >= every edge score into d

    float w = __expf(lrelu(g_as[d * 8 + head] + adv) - mp);
    float4 hv = ((const float4*)(g_h + (size_t)d * 128))[lane];
    float denom = w;
    float4 acc = make_float4(w * hv.x, w * hv.y, w * hv.z, w * hv.w);

    int e  = g_off[d];
    int e1 = g_off[d + 1];
    for (; e + 3 < e1; e += 4) {
        int s0 = g_csrc[e];
        int s1 = g_csrc[e + 1];
        int s2 = g_csrc[e + 2];
        int s3 = g_csrc[e + 3];
        float a0 = g_as[s0 * 8 + head];
        float a1 = g_as[s1 * 8 + head];
        float a2 = g_as[s2 * 8 + head];
        float a3 = g_as[s3 * 8 + head];
        float4 h0 = ((const float4*)(g_h + (size_t)s0 * 128))[lane];
        float4 h1 = ((const float4*)(g_h + (size_t)s1 * 128))[lane];
        float4 h2 = ((const float4*)(g_h + (size_t)s2 * 128))[lane];
        float4 h3 = ((const float4*)(g_h + (size_t)s3 * 128))[lane];
        float w0 = __expf(lrelu(a0 + adv) - mp);
        float w1 = __expf(lrelu(a1 + adv) - mp);
        float w2 = __expf(lrelu(a2 + adv) - mp);
        float w3 = __expf(lrelu(a3 + adv) - mp);
        denom += (w0 + w1) + (w2 + w3);
        acc.x = fmaf(w0, h0.x, acc.x); acc.y = fmaf(w0, h0.y, acc.y);
        acc.z = fmaf(w0, h0.z, acc.z); acc.w = fmaf(w0, h0.w, acc.w);
        acc.x = fmaf(w1, h1.x, acc.x); acc.y = fmaf(w1, h1.y, acc.y);
        acc.z = fmaf(w1, h1.z, acc.z); acc.w = fmaf(w1, h1.w, acc.w);
        acc.x = fmaf(w2, h2.x, acc.x); acc.y = fmaf(w2, h2.y, acc.y);
        acc.z = fmaf(w2, h2.z, acc.z); acc.w = fmaf(w2, h2.w, acc.w);
        acc.x = fmaf(w3, h3.x, acc.x); acc.y = fmaf(w3, h3.y, acc.y);
        acc.z = fmaf(w3, h3.z, acc.z); acc.w = fmaf(w3, h3.w, acc.w);
    }
    for (; e < e1; e++) {
        int s0 = g_csrc[e];
        float a0 = g_as[s0 * 8 + head];
        float4 h0 = ((const float4*)(g_h + (size_t)s0 * 128))[lane];
        float w0 = __expf(lrelu(a0 + adv) - mp);
        denom += w0;
        acc.x = fmaf(w0, h0.x, acc.x); acc.y = fmaf(w0, h0.y, acc.y);
        acc.z = fmaf(w0, h0.z, acc.z); acc.w = fmaf(w0, h0.w, acc.w);
    }

    float inv = 1.f / (denom + 1e-16f);
    float4 b = ((const float4*)bias)[lane];
    float4 v;
    v.x = acc.x * inv + b.x; v.y = acc.y * inv + b.y;
    v.z = acc.z * inv + b.z; v.w = acc.w * inv + b.w;
    v.x = v.x > 0.f ? v.x : expm1f(v.x);
    v.y = v.y > 0.f ? v.y : expm1f(v.y);
    v.z = v.z > 0.f ? v.z : expm1f(v.z);
    v.w = v.w > 0.f ? v.w : expm1f(v.w);
    float4* dst = (layer == 0) ? (float4*)(g_x2 + (size_t)d * 128)
                               : (float4*)(out + (size_t)d * 128);
    dst[lane] = v;
}

extern "C" void kernel_launch(void* const* d_in, const int* in_sizes, int n_in,
                              void* d_out, int out_size) {
    const float* x   = (const float*)d_in[0];
    const int*   ei  = (const int*)d_in[1];
    const float* W1  = (const float*)d_in[2];
    const float* as1 = (const float*)d_in[3];
    const float* ad1 = (const float*)d_in[4];
    const float* b1  = (const float*)d_in[5];
    const float* W2  = (const float*)d_in[6];
    const float* as2 = (const float*)d_in[7];
    const float* ad2 = (const float*)d_in[8];
    const float* b2  = (const float*)d_in[9];
    float* out = (float*)d_out;

    const int GB  = (NN + 63) / 64;
    const int NB4 = (NN / 4 + 255) / 256;
    const int EB4 = (NEDGE / 4 + 255) / 256;
    const int AG  = (int)(((size_t)NN * 32 + 255) / 256);

    // CSR build (serial; shared by both layers), also inits both gmax buffers
    zero_cnt<<<NB4, 256>>>();
    count_edges<<<EB4, 256>>>(ei);
    scan_offsets<<<1, SCAN_T>>>();
    scatter_edges<<<EB4, 256>>>(ei);

    // layer 1
    gemm_alpha<<<GB, 256>>>(x, 0, W1, as1, ad1);
    gat_gather<<<AG, 256>>>(b1, out, 0);

    // layer 2
    gemm_alpha<<<GB, 256>>>(x, 1, W2, as2, ad2);
    gat_gather<<<AG, 256>>>(b2, out, 1);
}

// round 15
// speedup vs baseline: 1.1252x; 1.1252x over previous
#include <cuda_runtime.h>
#include <math.h>

#define NN 50000
#define NEDGE 800000
#define F 128
#define SCAN_T 1024
#define CHUNK ((NN + SCAN_T - 1) / SCAN_T)

// ---- scratch (static device globals; no allocation anywhere) ----
__device__ float g_h[(size_t)NN * F];     // transformed features
__device__ float g_x2[(size_t)NN * F];    // layer-2 input
__device__ float g_as[NN * 8];            // alpha_src per node/head
__device__ float g_ad[NN * 8];            // alpha_dst per node/head
__device__ float g_gmax[2][8];            // per-layer global per-head max of g_as
__device__ int   g_cnt[NN];               // in-degree counts
__device__ int   g_off[NN + 1];           // CSR offsets (by dst)
__device__ int   g_cur[NN];               // scatter cursors
__device__ int   g_csrc[NEDGE];           // CSR src indices

__device__ __forceinline__ float lrelu(float v) { return v >= 0.f ? v : 0.2f * v; }

__device__ __forceinline__ void atomicMaxF(float* a, float v) {
    if (v >= 0.f) atomicMax((int*)a, __float_as_int(v));
    else          atomicMin((unsigned int*)a, __float_as_uint(v));
}
__device__ __forceinline__ void atomicMaxFs(float* a, float v) {  // shared-mem
    if (v >= 0.f) atomicMax((int*)a, __float_as_int(v));
    else          atomicMin((unsigned int*)a, __float_as_uint(v));
}

// ================= CSR build (once per launch, shared by both layers) ========
// also initializes both layers' gmax buffers (takes resets off the layer path)
__global__ void zero_cnt() {
    int i = blockIdx.x * blockDim.x + threadIdx.x;
    if (i < NN) g_cnt[i] = 0;
    if (i < 16) g_gmax[i >> 3][i & 7] = -INFINITY;
}

__global__ void count_edges(const int* __restrict__ ei) {
    int e = blockIdx.x * blockDim.x + threadIdx.x;
    if (e < NEDGE) atomicAdd(&g_cnt[ei[NEDGE + e]], 1);
}

__global__ void scan_offsets() {
    __shared__ int partial[SCAN_T];
    int t = threadIdx.x;
    int start = t * CHUNK;
    int end = min(start + CHUNK, NN);
    int s = 0;
    for (int i = start; i < end; i++) s += g_cnt[i];
    partial[t] = s;
    __syncthreads();
    for (int off = 1; off < SCAN_T; off <<= 1) {
        int v = (t >= off) ? partial[t - off] : 0;
        __syncthreads();
        partial[t] += v;
        __syncthreads();
    }
    int run = partial[t] - s;   // exclusive prefix at chunk start
    for (int i = start; i < end; i++) {
        g_off[i] = run;
        g_cur[i] = run;
        run += g_cnt[i];
    }
    if (t == SCAN_T - 1) g_off[NN] = partial[SCAN_T - 1];
}

__global__ void scatter_edges(const int* __restrict__ ei) {
    int e = blockIdx.x * blockDim.x + threadIdx.x;
    if (e >= NEDGE) return;
    int s = ei[e], d = ei[NEDGE + e];
    int pos = atomicAdd(&g_cur[d], 1);
    g_csrc[pos] = s;
}

// ================= GEMM h = x @ W, fused alpha + gmax epilogue ===============
// block = 256 threads (8 warps), 32 rows/block, 4 rows/warp, 4 cols/lane
// (proven R13 scalar configuration + in-epilogue per-head gmax reduction)
__global__ void gemm_alpha(const float* __restrict__ xin, int layer,
                           const float* __restrict__ W,
                           const float* __restrict__ asr,
                           const float* __restrict__ adr)
{
    const float* x = layer ? g_x2 : xin;
    __shared__ float Wsh[64 * 128];
    __shared__ float Xsh[32 * 64];
    __shared__ float red[8];
    int tid  = threadIdx.x;
    int warp = tid >> 5, lane = tid & 31;
    int row0 = blockIdx.x * 32;
    if (tid < 8) red[tid] = -INFINITY;
    float acc[4][4];
#pragma unroll
    for (int r = 0; r < 4; r++)
#pragma unroll
        for (int c = 0; c < 4; c++) acc[r][c] = 0.f;

    for (int kb = 0; kb < 128; kb += 64) {
        for (int i = tid; i < 2048; i += 256)
            ((float4*)Wsh)[i] = ((const float4*)(W + kb * 128))[i];
        for (int i = tid; i < 512; i += 256) {
            int r = i >> 4, c4 = i & 15;
            int row = row0 + r;
            float4 v = make_float4(0.f, 0.f, 0.f, 0.f);
            if (row < NN) v = *(const float4*)(x + (size_t)row * 128 + kb + c4 * 4);
            ((float4*)Xsh)[i] = v;
        }
        __syncthreads();
#pragma unroll 8
        for (int k = 0; k < 64; k++) {
            float4 wv = ((float4*)Wsh)[k * 32 + lane];
#pragma unroll
            for (int r = 0; r < 4; r++) {
                float xv = Xsh[(warp * 4 + r) * 64 + k];
                acc[r][0] = fmaf(xv, wv.x, acc[r][0]);
                acc[r][1] = fmaf(xv, wv.y, acc[r][1]);
                acc[r][2] = fmaf(xv, wv.z, acc[r][2]);
                acc[r][3] = fmaf(xv, wv.w, acc[r][3]);
            }
        }
        __syncthreads();
    }

    float4 a_s = ((const float4*)asr)[lane];
    float4 a_d = ((const float4*)adr)[lane];
#pragma unroll
    for (int r = 0; r < 4; r++) {
        int row = row0 + warp * 4 + r;
        if (row >= NN) continue;
        float4 v = make_float4(acc[r][0], acc[r][1], acc[r][2], acc[r][3]);
        ((float4*)(g_h + (size_t)row * 128))[lane] = v;
        float ps = v.x * a_s.x + v.y * a_s.y + v.z * a_s.z + v.w * a_s.w;
        float pd = v.x * a_d.x + v.y * a_d.y + v.z * a_d.z + v.w * a_d.w;
        ps += __shfl_down_sync(0xffffffffu, ps, 2);
        ps += __shfl_down_sync(0xffffffffu, ps, 1);
        pd += __shfl_down_sync(0xffffffffu, pd, 2);
        pd += __shfl_down_sync(0xffffffffu, pd, 1);
        if ((lane & 3) == 0) {
            int head = lane >> 2;
            g_as[row * 8 + head] = ps;
            g_ad[row * 8 + head] = pd;
            atomicMaxFs(&red[head], ps);
        }
    }
    __syncthreads();
    if (tid < 8) atomicMaxF(&g_gmax[layer][tid], red[tid]);
}

// ================= gather aggregation (warp per dst node) ====================
// lane owns 4 channels (head = lane>>2); register accumulation; no atomics.
// Fused: softmax (shifted), normalize, +bias, ELU, output write.
__global__ void gat_gather(const float* __restrict__ bias,
                           float* __restrict__ out, int layer)
{
    int d    = (int)((blockIdx.x * (size_t)blockDim.x + threadIdx.x) >> 5);
    int lane = threadIdx.x & 31;
    if (d >= NN) return;
    int head = lane >> 2;

    float adv = g_ad[d * 8 + head];
    float mp  = lrelu(g_gmax[layer][head] + adv);   // >= every edge score into d

    float w = __expf(lrelu(g_as[d * 8 + head] + adv) - mp);
    float4 hv = ((const float4*)(g_h + (size_t)d * 128))[lane];
    float denom = w;
    float4 acc = make_float4(w * hv.x, w * hv.y, w * hv.z, w * hv.w);

    int e  = g_off[d];
    int e1 = g_off[d + 1];
    // unroll x8: 8 outstanding (csrc -> as,h) chains per warp for max MLP
    for (; e + 7 < e1; e += 8) {
        int s[8];
#pragma unroll
        for (int q = 0; q < 8; q++) s[q] = g_csrc[e + q];
        float a[8];
#pragma unroll
        for (int q = 0; q < 8; q++) a[q] = g_as[s[q] * 8 + head];
        float4 hh[8];
#pragma unroll
        for (int q = 0; q < 8; q++)
            hh[q] = ((const float4*)(g_h + (size_t)s[q] * 128))[lane];
#pragma unroll
        for (int q = 0; q < 8; q++) {
            float wq = __expf(lrelu(a[q] + adv) - mp);
            denom += wq;
            acc.x = fmaf(wq, hh[q].x, acc.x);
            acc.y = fmaf(wq, hh[q].y, acc.y);
            acc.z = fmaf(wq, hh[q].z, acc.z);
            acc.w = fmaf(wq, hh[q].w, acc.w);
        }
    }
    for (; e + 3 < e1; e += 4) {
        int s0 = g_csrc[e];
        int s1 = g_csrc[e + 1];
        int s2 = g_csrc[e + 2];
        int s3 = g_csrc[e + 3];
        float a0 = g_as[s0 * 8 + head];
        float a1 = g_as[s1 * 8 + head];
        float a2 = g_as[s2 * 8 + head];
        float a3 = g_as[s3 * 8 + head];
        float4 h0 = ((const float4*)(g_h + (size_t)s0 * 128))[lane];
        float4 h1 = ((const float4*)(g_h + (size_t)s1 * 128))[lane];
        float4 h2 = ((const float4*)(g_h + (size_t)s2 * 128))[lane];
        float4 h3 = ((const float4*)(g_h + (size_t)s3 * 128))[lane];
        float w0 = __expf(lrelu(a0 + adv) - mp);
        float w1 = __expf(lrelu(a1 + adv) - mp);
        float w2 = __expf(lrelu(a2 + adv) - mp);
        float w3 = __expf(lrelu(a3 + adv) - mp);
        denom += (w0 + w1) + (w2 + w3);
        acc.x = fmaf(w0, h0.x, acc.x); acc.y = fmaf(w0, h0.y, acc.y);
        acc.z = fmaf(w0, h0.z, acc.z); acc.w = fmaf(w0, h0.w, acc.w);
        acc.x = fmaf(w1, h1.x, acc.x); acc.y = fmaf(w1, h1.y, acc.y);
        acc.z = fmaf(w1, h1.z, acc.z); acc.w = fmaf(w1, h1.w, acc.w);
        acc.x = fmaf(w2, h2.x, acc.x); acc.y = fmaf(w2, h2.y, acc.y);
        acc.z = fmaf(w2, h2.z, acc.z); acc.w = fmaf(w2, h2.w, acc.w);
        acc.x = fmaf(w3, h3.x, acc.x); acc.y = fmaf(w3, h3.y, acc.y);
        acc.z = fmaf(w3, h3.z, acc.z); acc.w = fmaf(w3, h3.w, acc.w);
    }
    for (; e < e1; e++) {
        int s0 = g_csrc[e];
        float a0 = g_as[s0 * 8 + head];
        float4 h0 = ((const float4*)(g_h + (size_t)s0 * 128))[lane];
        float w0 = __expf(lrelu(a0 + adv) - mp);
        denom += w0;
        acc.x = fmaf(w0, h0.x, acc.x); acc.y = fmaf(w0, h0.y, acc.y);
        acc.z = fmaf(w0, h0.z, acc.z); acc.w = fmaf(w0, h0.w, acc.w);
    }

    float inv = 1.f / (denom + 1e-16f);
    float4 b = ((const float4*)bias)[lane];
    float4 v;
    v.x = acc.x * inv + b.x; v.y = acc.y * inv + b.y;
    v.z = acc.z * inv + b.z; v.w = acc.w * inv + b.w;
    v.x = v.x > 0.f ? v.x : expm1f(v.x);
    v.y = v.y > 0.f ? v.y : expm1f(v.y);
    v.z = v.z > 0.f ? v.z : expm1f(v.z);
    v.w = v.w > 0.f ? v.w : expm1f(v.w);
    float4* dst = (layer == 0) ? (float4*)(g_x2 + (size_t)d * 128)
                               : (float4*)(out + (size_t)d * 128);
    dst[lane] = v;
}

extern "C" void kernel_launch(void* const* d_in, const int* in_sizes, int n_in,
                              void* d_out, int out_size) {
    const float* x   = (const float*)d_in[0];
    const int*   ei  = (const int*)d_in[1];
    const float* W1  = (const float*)d_in[2];
    const float* as1 = (const float*)d_in[3];
    const float* ad1 = (const float*)d_in[4];
    const float* b1  = (const float*)d_in[5];
    const float* W2  = (const float*)d_in[6];
    const float* as2 = (const float*)d_in[7];
    const float* ad2 = (const float*)d_in[8];
    const float* b2  = (const float*)d_in[9];
    float* out = (float*)d_out;

    const int GB = (NN + 31) / 32;
    const int NB = (NN + 255) / 256;
    const int EB = (NEDGE + 255) / 256;
    const int AG = (int)(((size_t)NN * 32 + 255) / 256);

    // CSR build (serial; shared by both layers), also inits both gmax buffers
    zero_cnt<<<NB, 256>>>();
    count_edges<<<EB, 256>>>(ei);
    scan_offsets<<<1, SCAN_T>>>();
    scatter_edges<<<EB, 256>>>(ei);

    // layer 1
    gemm_alpha<<<GB, 256>>>(x, 0, W1, as1, ad1);
    gat_gather<<<AG, 256>>>(b1, out, 0);

    // layer 2
    gemm_alpha<<<GB, 256>>>(x, 1, W2, as2, ad2);
    gat_gather<<<AG, 256>>>(b2, out, 1);
}

// round 16
// speedup vs baseline: 1.4634x; 1.3005x over previous
#include <cuda_runtime.h>
#include <math.h>

#define NN 50000
#define NEDGE 800000
#define F 128
#define SEG 256
#define NSEG ((NN + SEG - 1) / SEG)   // 196

// ---- scratch (static device globals; no allocation anywhere) ----
__device__ float g_h[(size_t)NN * F];     // transformed features
__device__ float g_x2[(size_t)NN * F];    // layer-2 input
__device__ float g_as[NN * 8];            // alpha_src per node/head
__device__ float g_ad[NN * 8];            // alpha_dst per node/head
__device__ float g_gmax[2][8];            // per-layer global per-head max of g_as
__device__ int   g_cnt[NN];               // in-degree counts
__device__ int   g_off[NN + 1];           // CSR offsets (by dst)
__device__ int   g_cur[NN];               // scatter cursors
__device__ int   g_csrc[NEDGE];           // CSR src indices
__device__ int   g_bsum[NSEG];            // per-segment sums
__device__ int   g_boff[NSEG];            // per-segment exclusive offsets

__device__ __forceinline__ float lrelu(float v) { return v >= 0.f ? v : 0.2f * v; }

__device__ __forceinline__ void atomicMaxF(float* a, float v) {
    if (v >= 0.f) atomicMax((int*)a, __float_as_int(v));
    else          atomicMin((unsigned int*)a, __float_as_uint(v));
}
__device__ __forceinline__ void atomicMaxFs(float* a, float v) {  // shared-mem
    if (v >= 0.f) atomicMax((int*)a, __float_as_int(v));
    else          atomicMin((unsigned int*)a, __float_as_uint(v));
}

// ================= CSR build (once per launch, shared by both layers) ========
__global__ void zero_cnt() {
    int i = blockIdx.x * blockDim.x + threadIdx.x;
    if (i < NN) g_cnt[i] = 0;
    if (i < 16) g_gmax[i >> 3][i & 7] = -INFINITY;
}

__global__ void count_edges(const int* __restrict__ ei) {
    int e = blockIdx.x * blockDim.x + threadIdx.x;
    if (e < NEDGE) atomicAdd(&g_cnt[ei[NEDGE + e]], 1);
}

// --- 3-phase multi-block exclusive scan of g_cnt -> g_off/g_cur ---
__global__ void scan_a() {   // grid NSEG, block SEG: per-segment sums
    __shared__ int sred[8];
    int tid = threadIdx.x, lane = tid & 31, warp = tid >> 5;
    int i = blockIdx.x * SEG + tid;
    int v = (i < NN) ? g_cnt[i] : 0;
    int s = v;
#pragma unroll
    for (int o = 16; o >= 1; o >>= 1) s += __shfl_xor_sync(0xffffffffu, s, o);
    if (lane == 0) sred[warp] = s;
    __syncthreads();
    if (tid == 0) {
        int t = 0;
#pragma unroll
        for (int w = 0; w < 8; w++) t += sred[w];
        g_bsum[blockIdx.x] = t;
    }
}

__global__ void scan_b() {   // 1 block, 256 threads: scan NSEG segment sums
    __shared__ int sh[256];
    int t = threadIdx.x;
    int v = (t < NSEG) ? g_bsum[t] : 0;
    sh[t] = v;
    __syncthreads();
    for (int o = 1; o < 256; o <<= 1) {
        int u = (t >= o) ? sh[t - o] : 0;
        __syncthreads();
        sh[t] += u;
        __syncthreads();
    }
    if (t < NSEG) g_boff[t] = sh[t] - v;      // exclusive
    if (t == 255) g_off[NN] = sh[255];
}

__global__ void scan_c() {   // grid NSEG, block SEG: per-segment exclusive scan
    __shared__ int sh[SEG];
    int t = threadIdx.x;
    int i = blockIdx.x * SEG + t;
    int v = (i < NN) ? g_cnt[i] : 0;
    sh[t] = v;
    __syncthreads();
    for (int o = 1; o < SEG; o <<= 1) {
        int u = (t >= o) ? sh[t - o] : 0;
        __syncthreads();
        sh[t] += u;
        __syncthreads();
    }
    if (i < NN) {
        int ex = sh[t] - v + g_boff[blockIdx.x];
        g_off[i] = ex;
        g_cur[i] = ex;
    }
}

__global__ void scatter_edges(const int* __restrict__ ei) {
    int e = blockIdx.x * blockDim.x + threadIdx.x;
    if (e >= NEDGE) return;
    int s = ei[e], d = ei[NEDGE + e];
    int pos = atomicAdd(&g_cur[d], 1);
    g_csrc[pos] = s;
}

// ================= GEMM h = x @ W, fused alpha + gmax epilogue ===============
// block = 256 threads (8 warps), 32 rows/block, 4 rows/warp, 4 cols/lane.
// k4-grouped inner loop: 8 LDS.128 per 64 FFMA (was 20 LDS).
__global__ void gemm_alpha(const float* __restrict__ xin, int layer,
                           const float* __restrict__ W,
                           const float* __restrict__ asr,
                           const float* __restrict__ adr)
{
    const float* x = layer ? g_x2 : xin;
    __shared__ float Wsh[64 * 128];
    __shared__ float Xsh[32 * 64];
    __shared__ float red[8];
    int tid  = threadIdx.x;
    int warp = tid >> 5, lane = tid & 31;
    int row0 = blockIdx.x * 32;
    if (tid < 8) red[tid] = -INFINITY;
    float acc[4][4];
#pragma unroll
    for (int r = 0; r < 4; r++)
#pragma unroll
        for (int c = 0; c < 4; c++) acc[r][c] = 0.f;

    for (int kb = 0; kb < 128; kb += 64) {
        for (int i = tid; i < 2048; i += 256)
            ((float4*)Wsh)[i] = ((const float4*)(W + kb * 128))[i];
        for (int i = tid; i < 512; i += 256) {
            int r = i >> 4, c4 = i & 15;
            int row = row0 + r;
            float4 v = make_float4(0.f, 0.f, 0.f, 0.f);
            if (row < NN) v = *(const float4*)(x + (size_t)row * 128 + kb + c4 * 4);
            ((float4*)Xsh)[i] = v;
        }
        __syncthreads();
        const float4* W4 = (const float4*)Wsh;
        const float4* X4 = (const float4*)Xsh;
#pragma unroll 4
        for (int k4 = 0; k4 < 16; k4++) {
            float4 wv0 = W4[(k4 * 4 + 0) * 32 + lane];
            float4 wv1 = W4[(k4 * 4 + 1) * 32 + lane];
            float4 wv2 = W4[(k4 * 4 + 2) * 32 + lane];
            float4 wv3 = W4[(k4 * 4 + 3) * 32 + lane];
#pragma unroll
            for (int r = 0; r < 4; r++) {
                float4 xv = X4[(warp * 4 + r) * 16 + k4];
                acc[r][0] = fmaf(xv.x, wv0.x, acc[r][0]);
                acc[r][1] = fmaf(xv.x, wv0.y, acc[r][1]);
                acc[r][2] = fmaf(xv.x, wv0.z, acc[r][2]);
                acc[r][3] = fmaf(xv.x, wv0.w, acc[r][3]);
                acc[r][0] = fmaf(xv.y, wv1.x, acc[r][0]);
                acc[r][1] = fmaf(xv.y, wv1.y, acc[r][1]);
                acc[r][2] = fmaf(xv.y, wv1.z, acc[r][2]);
                acc[r][3] = fmaf(xv.y, wv1.w, acc[r][3]);
                acc[r][0] = fmaf(xv.z, wv2.x, acc[r][0]);
                acc[r][1] = fmaf(xv.z, wv2.y, acc[r][1]);
                acc[r][2] = fmaf(xv.z, wv2.z, acc[r][2]);
                acc[r][3] = fmaf(xv.z, wv2.w, acc[r][3]);
                acc[r][0] = fmaf(xv.w, wv3.x, acc[r][0]);
                acc[r][1] = fmaf(xv.w, wv3.y, acc[r][1]);
                acc[r][2] = fmaf(xv.w, wv3.z, acc[r][2]);
                acc[r][3] = fmaf(xv.w, wv3.w, acc[r][3]);
            }
        }
        __syncthreads();
    }

    float4 a_s = ((const float4*)asr)[lane];
    float4 a_d = ((const float4*)adr)[lane];
#pragma unroll
    for (int r = 0; r < 4; r++) {
        int row = row0 + warp * 4 + r;
        if (row >= NN) continue;
        float4 v = make_float4(acc[r][0], acc[r][1], acc[r][2], acc[r][3]);
        ((float4*)(g_h + (size_t)row * 128))[lane] = v;
        float ps = v.x * a_s.x + v.y * a_s.y + v.z * a_s.z + v.w * a_s.w;
        float pd = v.x * a_d.x + v.y * a_d.y + v.z * a_d.z + v.w * a_d.w;
        ps += __shfl_down_sync(0xffffffffu, ps, 2);
        ps += __shfl_down_sync(0xffffffffu, ps, 1);
        pd += __shfl_down_sync(0xffffffffu, pd, 2);
        pd += __shfl_down_sync(0xffffffffu, pd, 1);
        if ((lane & 3) == 0) {
            int head = lane >> 2;
            g_as[row * 8 + head] = ps;
            g_ad[row * 8 + head] = pd;
            atomicMaxFs(&red[head], ps);
        }
    }
    __syncthreads();
    if (tid < 8) atomicMaxF(&g_gmax[layer][tid], red[tid]);
}

// ================= gather aggregation (warp per dst node) ====================
__global__ void gat_gather(const float* __restrict__ bias,
                           float* __restrict__ out, int layer)
{
    int d    = (int)((blockIdx.x * (size_t)blockDim.x + threadIdx.x) >> 5);
    int lane = threadIdx.x & 31;
    if (d >= NN) return;
    int head = lane >> 2;

    float adv = g_ad[d * 8 + head];
    float mp  = lrelu(g_gmax[layer][head] + adv);   // >= every edge score into d

    float w = __expf(lrelu(g_as[d * 8 + head] + adv) - mp);
    float4 hv = ((const float4*)(g_h + (size_t)d * 128))[lane];
    float denom = w;
    float4 acc = make_float4(w * hv.x, w * hv.y, w * hv.z, w * hv.w);

    int e  = g_off[d];
    int e1 = g_off[d + 1];
    // unroll x8: 8 outstanding (csrc -> as,h) chains per warp for max MLP
    for (; e + 7 < e1; e += 8) {
        int s[8];
#pragma unroll
        for (int q = 0; q < 8; q++) s[q] = g_csrc[e + q];
        float a[8];
#pragma unroll
        for (int q = 0; q < 8; q++) a[q] = g_as[s[q] * 8 + head];
        float4 hh[8];
#pragma unroll
        for (int q = 0; q < 8; q++)
            hh[q] = ((const float4*)(g_h + (size_t)s[q] * 128))[lane];
#pragma unroll
        for (int q = 0; q < 8; q++) {
            float wq = __expf(lrelu(a[q] + adv) - mp);
            denom += wq;
            acc.x = fmaf(wq, hh[q].x, acc.x);
            acc.y = fmaf(wq, hh[q].y, acc.y);
            acc.z = fmaf(wq, hh[q].z, acc.z);
            acc.w = fmaf(wq, hh[q].w, acc.w);
        }
    }
    for (; e + 3 < e1; e += 4) {
        int s0 = g_csrc[e];
        int s1 = g_csrc[e + 1];
        int s2 = g_csrc[e + 2];
        int s3 = g_csrc[e + 3];
        float a0 = g_as[s0 * 8 + head];
        float a1 = g_as[s1 * 8 + head];
        float a2 = g_as[s2 * 8 + head];
        float a3 = g_as[s3 * 8 + head];
        float4 h0 = ((const float4*)(g_h + (size_t)s0 * 128))[lane];
        float4 h1 = ((const float4*)(g_h + (size_t)s1 * 128))[lane];
        float4 h2 = ((const float4*)(g_h + (size_t)s2 * 128))[lane];
        float4 h3 = ((const float4*)(g_h + (size_t)s3 * 128))[lane];
        float w0 = __expf(lrelu(a0 + adv) - mp);
        float w1 = __expf(lrelu(a1 + adv) - mp);
        float w2 = __expf(lrelu(a2 + adv) - mp);
        float w3 = __expf(lrelu(a3 + adv) - mp);
        denom += (w0 + w1) + (w2 + w3);
        acc.x = fmaf(w0, h0.x, acc.x); acc.y = fmaf(w0, h0.y, acc.y);
        acc.z = fmaf(w0, h0.z, acc.z); acc.w = fmaf(w0, h0.w, acc.w);
        acc.x = fmaf(w1, h1.x, acc.x); acc.y = fmaf(w1, h1.y, acc.y);
        acc.z = fmaf(w1, h1.z, acc.z); acc.w = fmaf(w1, h1.w, acc.w);
        acc.x = fmaf(w2, h2.x, acc.x); acc.y = fmaf(w2, h2.y, acc.y);
        acc.z = fmaf(w2, h2.z, acc.z); acc.w = fmaf(w2, h2.w, acc.w);
        acc.x = fmaf(w3, h3.x, acc.x); acc.y = fmaf(w3, h3.y, acc.y);
        acc.z = fmaf(w3, h3.z, acc.z); acc.w = fmaf(w3, h3.w, acc.w);
    }
    for (; e < e1; e++) {
        int s0 = g_csrc[e];
        float a0 = g_as[s0 * 8 + head];
        float4 h0 = ((const float4*)(g_h + (size_t)s0 * 128))[lane];
        float w0 = __expf(lrelu(a0 + adv) - mp);
        denom += w0;
        acc.x = fmaf(w0, h0.x, acc.x); acc.y = fmaf(w0, h0.y, acc.y);
        acc.z = fmaf(w0, h0.z, acc.z); acc.w = fmaf(w0, h0.w, acc.w);
    }

    float inv = 1.f / (denom + 1e-16f);
    float4 b = ((const float4*)bias)[lane];
    float4 v;
    v.x = acc.x * inv + b.x; v.y = acc.y * inv + b.y;
    v.z = acc.z * inv + b.z; v.w = acc.w * inv + b.w;
    v.x = v.x > 0.f ? v.x : expm1f(v.x);
    v.y = v.y > 0.f ? v.y : expm1f(v.y);
    v.z = v.z > 0.f ? v.z : expm1f(v.z);
    v.w = v.w > 0.f ? v.w : expm1f(v.w);
    float4* dst = (layer == 0) ? (float4*)(g_x2 + (size_t)d * 128)
                               : (float4*)(out + (size_t)d * 128);
    dst[lane] = v;
}

extern "C" void kernel_launch(void* const* d_in, const int* in_sizes, int n_in,
                              void* d_out, int out_size) {
    const float* x   = (const float*)d_in[0];
    const int*   ei  = (const int*)d_in[1];
    const float* W1  = (const float*)d_in[2];
    const float* as1 = (const float*)d_in[3];
    const float* ad1 = (const float*)d_in[4];
    const float* b1  = (const float*)d_in[5];
    const float* W2  = (const float*)d_in[6];
    const float* as2 = (const float*)d_in[7];
    const float* ad2 = (const float*)d_in[8];
    const float* b2  = (const float*)d_in[9];
    float* out = (float*)d_out;

    const int GB = (NN + 31) / 32;
    const int NB = (NN + 255) / 256;
    const int EB = (NEDGE + 255) / 256;
    const int AG = (int)(((size_t)NN * 32 + 255) / 256);

    // CSR build (serial; shared by both layers), also inits both gmax buffers
    zero_cnt<<<NB, 256>>>();
    count_edges<<<EB, 256>>>(ei);
    scan_a<<<NSEG, SEG>>>();
    scan_b<<<1, 256>>>();
    scan_c<<<NSEG, SEG>>>();
    scatter_edges<<<EB, 256>>>(ei);

    // layer 1
    gemm_alpha<<<GB, 256>>>(x, 0, W1, as1, ad1);
    gat_gather<<<AG, 256>>>(b1, out, 0);

    // layer 2
    gemm_alpha<<<GB, 256>>>(x, 1, W2, as2, ad2);
    gat_gather<<<AG, 256>>>(b2, out, 1);
}